// round 7
// baseline (speedup 1.0000x reference)
#include <cuda_runtime.h>
#include <math.h>

#define B_    64
#define T_    512
#define E_    512
#define H_    1024
#define G4_   4096   /* 4*H */
#define TCH_  128    /* time chunk for xproj scratch */

// Scratch (alloc-free rule: __device__ globals).
// Xproj chunk layout: [(t % TCH_)*64 + b][4096]  -> 128 MB
__device__ float g_xproj[(size_t)B_ * TCH_ * G4_];
__device__ float g_hbuf[2][B_ * H_];                 // h ping-pong
__device__ float g_cst[B_ * H_];                     // c state

// ---------------- packed f32x2 helpers (bit-exact 2x fp32 FMA) --------------
__device__ __forceinline__ unsigned long long pk2(float x, float y) {
    unsigned long long r;
    unsigned int a = __float_as_uint(x), b = __float_as_uint(y);
    asm("mov.b64 %0, {%1,%2};" : "=l"(r) : "r"(a), "r"(b));
    return r;
}
__device__ __forceinline__ void upk2(unsigned long long v, float& x, float& y) {
    unsigned int a, b;
    asm("mov.b64 {%0,%1}, %2;" : "=r"(a), "=r"(b) : "l"(v));
    x = __uint_as_float(a); y = __uint_as_float(b);
}
__device__ __forceinline__ unsigned long long ffma2(unsigned long long a,
                                                    unsigned long long b,
                                                    unsigned long long c) {
    unsigned long long d;
    asm("fma.rn.f32x2 %0, %1, %2, %3;" : "=l"(d) : "l"(a), "l"(b), "l"(c));
    return d;
}

// ---------------------------- init: h0 = c0 = 0 -----------------------------
__global__ void init_state() {
    int i = blockIdx.x * blockDim.x + threadIdx.x;
    if (i < B_ * H_) { g_hbuf[0][i] = 0.f; g_cst[i] = 0.f; }
}

// ---------------- Phase 1: Xproj chunk = emb[src] @ W_ih + bias -------------
// GEMM over one time chunk: M = TCH_*64 = 8192 (m_local = (t-t0)*64 + b),
// N=4096, K=512. BM=128, BN=64, BK=16, 256 thr, 8x4 per-thread microtile,
// row pairs packed in f32x2.
__global__ __launch_bounds__(256) void xproj_gemm(const int* __restrict__ src,
                                                  const float* __restrict__ emb,
                                                  const float* __restrict__ Wih,
                                                  const float* __restrict__ bias,
                                                  int t0) {
    __shared__ __align__(16) float As[16][132];   // [k][m], padded
    __shared__ __align__(16) float Bs[16][64];    // [k][n]
    __shared__ int srow[128];

    const int tid = threadIdx.x;
    const int m0 = blockIdx.y * 128;              // local m within chunk
    const int n0 = blockIdx.x * 64;

    if (tid < 128) {
        int m = m0 + tid;
        int b = m & 63, t = t0 + (m >> 6);
        srow[tid] = src[b * T_ + t];              // source[b][t]
    }
    __syncthreads();

    const int ty = tid >> 4;                      // 0..15 -> rows ty*8..+7
    const int tx = tid & 15;                      // 0..15 -> cols tx*4..+3

    unsigned long long acc[4][4];
    #pragma unroll
    for (int i = 0; i < 4; i++)
        #pragma unroll
        for (int j = 0; j < 4; j++) acc[i][j] = 0ull;

    for (int e0 = 0; e0 < E_; e0 += 16) {
        // load A tile (gathered embedding rows), transposed into SMEM
        #pragma unroll
        for (int i = 0; i < 2; i++) {
            int idx = tid + i * 256;              // 0..511
            int row = idx >> 2, c4 = idx & 3;
            float4 v = *reinterpret_cast<const float4*>(
                &emb[(size_t)srow[row] * E_ + e0 + c4 * 4]);
            As[c4 * 4 + 0][row] = v.x; As[c4 * 4 + 1][row] = v.y;
            As[c4 * 4 + 2][row] = v.z; As[c4 * 4 + 3][row] = v.w;
        }
        // load B tile
        {
            int row = tid >> 4, c4 = tid & 15;
            *reinterpret_cast<float4*>(&Bs[row][c4 * 4]) =
                *reinterpret_cast<const float4*>(
                    &Wih[(size_t)(e0 + row) * G4_ + n0 + c4 * 4]);
        }
        __syncthreads();

        #pragma unroll
        for (int kk = 0; kk < 16; kk++) {
            ulonglong2 a01 = *reinterpret_cast<ulonglong2*>(&As[kk][ty * 8]);
            ulonglong2 a23 = *reinterpret_cast<ulonglong2*>(&As[kk][ty * 8 + 4]);
            unsigned long long a2[4] = {a01.x, a01.y, a23.x, a23.y};
            float4 bv = *reinterpret_cast<float4*>(&Bs[kk][tx * 4]);
            unsigned long long bb[4] = {pk2(bv.x, bv.x), pk2(bv.y, bv.y),
                                        pk2(bv.z, bv.z), pk2(bv.w, bv.w)};
            #pragma unroll
            for (int i = 0; i < 4; i++)
                #pragma unroll
                for (int j = 0; j < 4; j++)
                    acc[i][j] = ffma2(a2[i], bb[j], acc[i][j]);
        }
        __syncthreads();
    }

    float4 b4 = *reinterpret_cast<const float4*>(&bias[n0 + tx * 4]);
    #pragma unroll
    for (int rp = 0; rp < 4; rp++) {
        float r0[4], r1[4];
        #pragma unroll
        for (int j = 0; j < 4; j++) upk2(acc[rp][j], r0[j], r1[j]);
        int m = m0 + ty * 8 + rp * 2;
        float4 o0 = make_float4(r0[0] + b4.x, r0[1] + b4.y, r0[2] + b4.z, r0[3] + b4.w);
        float4 o1 = make_float4(r1[0] + b4.x, r1[1] + b4.y, r1[2] + b4.z, r1[3] + b4.w);
        *reinterpret_cast<float4*>(&g_xproj[(size_t)m * G4_ + n0 + tx * 4]) = o0;
        *reinterpret_cast<float4*>(&g_xproj[(size_t)(m + 1) * G4_ + n0 + tx * 4]) = o1;
    }
}

// ---------------- Phase 2: one launch per timestep --------------------------
// Block p owns hidden units u0 = p*8..p*8+7 -> 32 W_hh columns (4 gates x 8),
// all 64 batches. Computes z = Xproj[t] + h_in @ W_hh, then the gate update,
// writing h_out (ping-pong) and c (in-place, exclusively owned cells).
__global__ __launch_bounds__(256) void lstm_step(const float* __restrict__ Whh,
                                                 int t) {
    __shared__ __align__(16) float hs[32][68];    // [k][b], padded
    __shared__ __align__(16) float ws[32][32];    // [k][c], c = gate*8 + unit
    __shared__ float zbuf[64][33];                // [b][c], padded

    const int tid = threadIdx.x;
    const int u0 = blockIdx.x * 8;
    const float* h_in = g_hbuf[t & 1];
    float* h_out = g_hbuf[(t + 1) & 1];

    const int bq = tid >> 4;                      // 0..15 -> batches bq*4..+3
    const int cp = tid & 15;                      // 0..15 -> cols cp*2, cp*2+1

    unsigned long long acc[2][2] = {{0ull, 0ull}, {0ull, 0ull}};

    for (int k0 = 0; k0 < H_; k0 += 32) {
        #pragma unroll
        for (int i = 0; i < 2; i++) {
            int idx = tid + i * 256;              // 0..511
            int b = idx >> 3, q = idx & 7;
            float4 v = *reinterpret_cast<const float4*>(&h_in[b * H_ + k0 + q * 4]);
            hs[q * 4 + 0][b] = v.x; hs[q * 4 + 1][b] = v.y;
            hs[q * 4 + 2][b] = v.z; hs[q * 4 + 3][b] = v.w;
        }
        {
            int k = tid >> 3, q = tid & 7;        // k 0..31, q 0..7
            int g = q >> 1, off = (q & 1) * 4;    // c = q*4..q*4+3 -> gate g
            *reinterpret_cast<float4*>(&ws[k][q * 4]) =
                *reinterpret_cast<const float4*>(
                    &Whh[(size_t)(k0 + k) * G4_ + g * H_ + u0 + off]);
        }
        __syncthreads();

        #pragma unroll 8
        for (int k = 0; k < 32; k++) {
            ulonglong2 hp = *reinterpret_cast<ulonglong2*>(&hs[k][bq * 4]);
            float2 wv = *reinterpret_cast<float2*>(&ws[k][cp * 2]);
            unsigned long long w0 = pk2(wv.x, wv.x);
            unsigned long long w1 = pk2(wv.y, wv.y);
            acc[0][0] = ffma2(hp.x, w0, acc[0][0]);
            acc[0][1] = ffma2(hp.x, w1, acc[0][1]);
            acc[1][0] = ffma2(hp.y, w0, acc[1][0]);
            acc[1][1] = ffma2(hp.y, w1, acc[1][1]);
        }
        __syncthreads();
    }

    // z = acc + Xproj, staged in SMEM so each (b,u) cell sees all 4 gates
    const float* Xp = g_xproj + (size_t)(t % TCH_) * (B_ * G4_);
    const int c0 = cp * 2;                              // even: c0,c0+1 same gate
    const int col0 = (c0 >> 3) * H_ + u0 + (c0 & 7);    // global column of c0
    #pragma unroll
    for (int bp = 0; bp < 2; bp++) {
        float v0, v1, x0, x1;
        upk2(acc[bp][0], v0, v1);
        upk2(acc[bp][1], x0, x1);
        int b0 = bq * 4 + bp * 2;
        zbuf[b0][c0]         = v0 + Xp[(size_t)b0 * G4_ + col0];
        zbuf[b0 + 1][c0]     = v1 + Xp[(size_t)(b0 + 1) * G4_ + col0];
        zbuf[b0][c0 + 1]     = x0 + Xp[(size_t)b0 * G4_ + col0 + 1];
        zbuf[b0 + 1][c0 + 1] = x1 + Xp[(size_t)(b0 + 1) * G4_ + col0 + 1];
    }
    __syncthreads();

    // gate update: 512 cells (64 b x 8 u) -> 2 per thread
    #pragma unroll
    for (int s = 0; s < 2; s++) {
        int idx = tid + s * 256;
        int b = idx >> 3, iu = idx & 7;
        float zi = zbuf[b][iu];
        float zf = zbuf[b][8 + iu];
        float zg = zbuf[b][16 + iu];
        float zo = zbuf[b][24 + iu];
        float ig = 1.f / (1.f + expf(-zi));
        float fg = 1.f / (1.f + expf(-zf));
        float gg = tanhf(zg);
        float og = 1.f / (1.f + expf(-zo));
        int off = b * H_ + u0 + iu;
        float cn = fg * g_cst[off] + ig * gg;
        g_cst[off] = cn;
        h_out[off] = og * tanhf(cn);
    }
}

// ------------------------------- output -------------------------------------
// After t=511, h lives in g_hbuf[(511+1)&1] == g_hbuf[0]. Output = [h_T ; c_T].
__global__ void write_out(float* __restrict__ out) {
    int i = blockIdx.x * blockDim.x + threadIdx.x;
    if (i < B_ * H_) {
        out[i] = g_hbuf[0][i];
        out[B_ * H_ + i] = g_cst[i];
    }
}

extern "C" void kernel_launch(void* const* d_in, const int* in_sizes, int n_in,
                              void* d_out, int out_size) {
    (void)in_sizes; (void)n_in; (void)out_size;
    const int*   src  = (const int*)d_in[0];
    const float* emb  = (const float*)d_in[1];
    const float* Wih  = (const float*)d_in[2];
    const float* Whh  = (const float*)d_in[3];
    const float* bias = (const float*)d_in[4];
    float* out = (float*)d_out;

    init_state<<<(B_ * H_ + 255) / 256, 256>>>();
    for (int t0 = 0; t0 < T_; t0 += TCH_) {
        xproj_gemm<<<dim3(G4_ / 64, (TCH_ * B_) / 128), 256>>>(src, emb, Wih,
                                                               bias, t0);
        for (int t = t0; t < t0 + TCH_; t++)
            lstm_step<<<H_ / 8, 256>>>(Whh, t);
    }
    write_out<<<(B_ * H_ + 255) / 256, 256>>>(out);
}

// round 9
// speedup vs baseline: 1.5201x; 1.5201x over previous
#include <cuda_runtime.h>
#include <math.h>

#define B_    64
#define T_    512
#define E_    512
#define H_    1024
#define G4_   4096   /* 4*H */
#define TCH_  128    /* time chunk (xproj scratch + persistent span) */
#define NBLK_ 128    /* persistent grid: 1024 units / 8 per block */
#define UPB_  8      /* hidden units per block */

// ---- global scratch (alloc-free rule: __device__ globals) ----
__device__ float g_xproj[(size_t)B_ * TCH_ * G4_];   // 128 MB chunk slab
__device__ float g_hbuf[2][B_ * H_];                 // h ping-pong
__device__ float g_cst[B_ * H_];                     // c state
__device__ unsigned g_bar[T_];                       // per-step arrival counters

// ---------------- packed f32x2 helpers (bit-exact 2x fp32 FMA) --------------
__device__ __forceinline__ unsigned long long pk2(float x, float y) {
    unsigned long long r;
    unsigned int a = __float_as_uint(x), b = __float_as_uint(y);
    asm("mov.b64 %0, {%1,%2};" : "=l"(r) : "r"(a), "r"(b));
    return r;
}
__device__ __forceinline__ void upk2(unsigned long long v, float& x, float& y) {
    unsigned int a, b;
    asm("mov.b64 {%0,%1}, %2;" : "=r"(a), "=r"(b) : "l"(v));
    x = __uint_as_float(a); y = __uint_as_float(b);
}
__device__ __forceinline__ unsigned long long ffma2(unsigned long long a,
                                                    unsigned long long b,
                                                    unsigned long long c) {
    unsigned long long d;
    asm("fma.rn.f32x2 %0, %1, %2, %3;" : "=l"(d) : "l"(a), "l"(b), "l"(c));
    return d;
}

// ---------------------------- init ------------------------------------------
__global__ void init_state() {
    int i = blockIdx.x * blockDim.x + threadIdx.x;
    if (i < B_ * H_) { g_hbuf[0][i] = 0.f; g_cst[i] = 0.f; }
    if (i < T_) g_bar[i] = 0u;
}

// ---------------- Phase 1: Xproj chunk = emb[src] @ W_ih + bias -------------
__global__ __launch_bounds__(256) void xproj_gemm(const int* __restrict__ src,
                                                  const float* __restrict__ emb,
                                                  const float* __restrict__ Wih,
                                                  const float* __restrict__ bias,
                                                  int t0) {
    __shared__ __align__(16) float As[16][132];
    __shared__ __align__(16) float Bs[16][64];
    __shared__ int srow[128];

    const int tid = threadIdx.x;
    const int m0 = blockIdx.y * 128;
    const int n0 = blockIdx.x * 64;

    if (tid < 128) {
        int m = m0 + tid;
        int b = m & 63, t = t0 + (m >> 6);
        srow[tid] = src[b * T_ + t];
    }
    __syncthreads();

    const int ty = tid >> 4;
    const int tx = tid & 15;

    unsigned long long acc[4][4];
    #pragma unroll
    for (int i = 0; i < 4; i++)
        #pragma unroll
        for (int j = 0; j < 4; j++) acc[i][j] = 0ull;

    for (int e0 = 0; e0 < E_; e0 += 16) {
        #pragma unroll
        for (int i = 0; i < 2; i++) {
            int idx = tid + i * 256;
            int row = idx >> 2, c4 = idx & 3;
            float4 v = *reinterpret_cast<const float4*>(
                &emb[(size_t)srow[row] * E_ + e0 + c4 * 4]);
            As[c4 * 4 + 0][row] = v.x; As[c4 * 4 + 1][row] = v.y;
            As[c4 * 4 + 2][row] = v.z; As[c4 * 4 + 3][row] = v.w;
        }
        {
            int row = tid >> 4, c4 = tid & 15;
            *reinterpret_cast<float4*>(&Bs[row][c4 * 4]) =
                *reinterpret_cast<const float4*>(
                    &Wih[(size_t)(e0 + row) * G4_ + n0 + c4 * 4]);
        }
        __syncthreads();

        #pragma unroll
        for (int kk = 0; kk < 16; kk++) {
            ulonglong2 a01 = *reinterpret_cast<ulonglong2*>(&As[kk][ty * 8]);
            ulonglong2 a23 = *reinterpret_cast<ulonglong2*>(&As[kk][ty * 8 + 4]);
            unsigned long long a2[4] = {a01.x, a01.y, a23.x, a23.y};
            float4 bv = *reinterpret_cast<float4*>(&Bs[kk][tx * 4]);
            unsigned long long bb[4] = {pk2(bv.x, bv.x), pk2(bv.y, bv.y),
                                        pk2(bv.z, bv.z), pk2(bv.w, bv.w)};
            #pragma unroll
            for (int i = 0; i < 4; i++)
                #pragma unroll
                for (int j = 0; j < 4; j++)
                    acc[i][j] = ffma2(a2[i], bb[j], acc[i][j]);
        }
        __syncthreads();
    }

    float4 b4 = *reinterpret_cast<const float4*>(&bias[n0 + tx * 4]);
    #pragma unroll
    for (int rp = 0; rp < 4; rp++) {
        float r0[4], r1[4];
        #pragma unroll
        for (int j = 0; j < 4; j++) upk2(acc[rp][j], r0[j], r1[j]);
        int m = m0 + ty * 8 + rp * 2;
        float4 o0 = make_float4(r0[0] + b4.x, r0[1] + b4.y, r0[2] + b4.z, r0[3] + b4.w);
        float4 o1 = make_float4(r1[0] + b4.x, r1[1] + b4.y, r1[2] + b4.z, r1[3] + b4.w);
        *reinterpret_cast<float4*>(&g_xproj[(size_t)m * G4_ + n0 + tx * 4]) = o0;
        *reinterpret_cast<float4*>(&g_xproj[(size_t)(m + 1) * G4_ + n0 + tx * 4]) = o1;
    }
}

// ---------------- Phase 2: persistent LSTM over a 128-step chunk ------------
// grid = 128 blocks (all resident, 1/SM). Block p owns units u0=p*8 ->
// 32 W_hh columns (4 gates x 8 units) held in SMEM for the launch.
// Per step: z = h_in @ Whh (8-way k-split over warps, 8b x 8c microtile,
// register-prefetched single hs buffer) + smem reduction + Xproj + gates,
// then an acquire/release grid barrier.
//
// SMEM map (dynamic, NO overlaps):
//   [0,      131072)  ws[1024][32]   weight slice
//   [131072, 148480)  hs[64][68]     h chunk, transposed [k][b]
//   [148480, 214016)  zs[8][64][32]  per-k-group partials
//   [214016, 222208)  zf[64][32]     reduced z
//   [222208, 224256)  cs[512]        block-private c state
#define SMEM_BYTES_ 224256

__global__ __launch_bounds__(256, 1) void lstm_chunk(const float* __restrict__ Whh,
                                                     int s0) {
    extern __shared__ __align__(16) char smem[];
    float* ws = (float*)smem;                    // [k][c], c = g*8 + j
    float* hs = (float*)(smem + 131072);         // [k][b], stride 68
    float* zs = (float*)(smem + 148480);         // [kg][b][c]
    float* zf = (float*)(smem + 214016);         // [b][c]
    float* cs = (float*)(smem + 222208);         // [b*8 + j]

    const int tid  = threadIdx.x;
    const int u0   = blockIdx.x * UPB_;
    const int kg   = tid >> 5;                   // warp = k-group 0..7
    const int lane = tid & 31;
    const int bpos = lane >> 2;                  // 0..7 -> batches bpos*8..+8
    const int cpos = lane & 3;                   // 0..3 -> cols cpos*8..+8

    // ---- load Whh slice into smem (once per launch) ----
    #pragma unroll
    for (int i = 0; i < 32; i++) {
        int idx = tid + i * 256;                 // 0..8191
        int k = idx >> 3, rem = idx & 7, g = rem >> 1, h4 = rem & 1;
        float4 v = *reinterpret_cast<const float4*>(
            &Whh[(size_t)k * G4_ + g * H_ + u0 + h4 * 4]);
        *reinterpret_cast<float4*>(&ws[k * 32 + g * 8 + h4 * 4]) = v;
    }
    // ---- load block-private c state ----
    #pragma unroll
    for (int i = 0; i < 2; i++) {
        int idx = tid + i * 256;
        cs[idx] = g_cst[(idx >> 3) * H_ + u0 + (idx & 7)];
    }
    __syncthreads();

    // thread's staging slots for the h transpose: (b, kq) pairs
    const int sb0 = tid >> 4;                    // slot q=0: b, kq
    const int sk0 = tid & 15;

    for (int ls = 0; ls < TCH_; ls++) {
        const int s = s0 + ls;
        const float* __restrict__ h_in  = g_hbuf[s & 1];
        float* __restrict__       h_out = g_hbuf[(s + 1) & 1];
        const float* __restrict__ Xp    = g_xproj + (size_t)ls * (B_ * G4_);

        unsigned long long acc[4][8];
        #pragma unroll
        for (int a = 0; a < 4; a++)
            #pragma unroll
            for (int c = 0; c < 8; c++) acc[a][c] = 0ull;

        // preload chunk 0 (registers only)
        float4 r[4];
        #pragma unroll
        for (int q = 0; q < 4; q++) {
            int slot = tid + q * 256;
            r[q] = __ldcg(reinterpret_cast<const float4*>(
                &h_in[(slot >> 4) * H_ + (slot & 15) * 4]));
        }

        for (int ch = 0; ch < 16; ch++) {
            __syncthreads();   // prior chunk's hs readers are done
            // stage chunk ch into hs (transposed [k][b])
            #pragma unroll
            for (int q = 0; q < 4; q++) {
                int slot = tid + q * 256;
                float* hp = hs + ((slot & 15) * 4) * 68 + (slot >> 4);
                hp[0] = r[q].x; hp[68] = r[q].y; hp[136] = r[q].z; hp[204] = r[q].w;
            }
            // prefetch chunk ch+1 (overlaps the compute below)
            if (ch < 15) {
                #pragma unroll
                for (int q = 0; q < 4; q++) {
                    int slot = tid + q * 256;
                    r[q] = __ldcg(reinterpret_cast<const float4*>(
                        &h_in[(slot >> 4) * H_ + (ch + 1) * 64 + (slot & 15) * 4]));
                }
            }
            __syncthreads();   // hs filled

            const float* wbase = ws + (ch * 64) * 32;
            #pragma unroll
            for (int kk = 0; kk < 8; kk++) {
                const int kl = kg * 8 + kk;
                const float* hp = hs + kl * 68 + bpos * 8;
                ulonglong2 h01 = *reinterpret_cast<const ulonglong2*>(hp);
                ulonglong2 h23 = *reinterpret_cast<const ulonglong2*>(hp + 4);
                const float* wp = wbase + kl * 32 + cpos * 8;
                float4 wa = *reinterpret_cast<const float4*>(wp);
                float4 wb = *reinterpret_cast<const float4*>(wp + 4);
                float wv[8] = {wa.x, wa.y, wa.z, wa.w, wb.x, wb.y, wb.z, wb.w};
                #pragma unroll
                for (int ci = 0; ci < 8; ci++) {
                    unsigned long long wd = pk2(wv[ci], wv[ci]);
                    acc[0][ci] = ffma2(h01.x, wd, acc[0][ci]);
                    acc[1][ci] = ffma2(h01.y, wd, acc[1][ci]);
                    acc[2][ci] = ffma2(h23.x, wd, acc[2][ci]);
                    acc[3][ci] = ffma2(h23.y, wd, acc[3][ci]);
                }
            }
        }

        // ---- write k-group partials to dedicated zs (no overlap with hs) ----
        #pragma unroll
        for (int bp = 0; bp < 4; bp++) {
            float lo[8], hi[8];
            #pragma unroll
            for (int ci = 0; ci < 8; ci++) upk2(acc[bp][ci], lo[ci], hi[ci]);
            int b0 = bpos * 8 + bp * 2;
            float* z0 = zs + kg * 2048 + b0 * 32 + cpos * 8;
            *reinterpret_cast<float4*>(z0)      = make_float4(lo[0], lo[1], lo[2], lo[3]);
            *reinterpret_cast<float4*>(z0 + 4)  = make_float4(lo[4], lo[5], lo[6], lo[7]);
            *reinterpret_cast<float4*>(z0 + 32) = make_float4(hi[0], hi[1], hi[2], hi[3]);
            *reinterpret_cast<float4*>(z0 + 36) = make_float4(hi[4], hi[5], hi[6], hi[7]);
        }
        __syncthreads();

        // ---- reduce over k-groups + add Xproj; thread owns cells tid*8..+8 ----
        {
            float4 za = make_float4(0.f, 0.f, 0.f, 0.f);
            float4 zb = make_float4(0.f, 0.f, 0.f, 0.f);
            #pragma unroll
            for (int kg2 = 0; kg2 < 8; kg2++) {
                float4 p0 = *reinterpret_cast<const float4*>(&zs[kg2 * 2048 + tid * 8]);
                float4 p1 = *reinterpret_cast<const float4*>(&zs[kg2 * 2048 + tid * 8 + 4]);
                za.x += p0.x; za.y += p0.y; za.z += p0.z; za.w += p0.w;
                zb.x += p1.x; zb.y += p1.y; zb.z += p1.z; zb.w += p1.w;
            }
            int b = tid >> 2, g = tid & 3;
            const float* xp = &Xp[(size_t)b * G4_ + g * H_ + u0];
            float4 x0 = __ldg(reinterpret_cast<const float4*>(xp));
            float4 x1 = __ldg(reinterpret_cast<const float4*>(xp + 4));
            za.x += x0.x; za.y += x0.y; za.z += x0.z; za.w += x0.w;
            zb.x += x1.x; zb.y += x1.y; zb.z += x1.z; zb.w += x1.w;
            *reinterpret_cast<float4*>(&zf[b * 32 + g * 8])     = za;
            *reinterpret_cast<float4*>(&zf[b * 32 + g * 8 + 4]) = zb;
        }
        __syncthreads();

        // ---- gate update: 2 cells per thread ----
        #pragma unroll
        for (int s2 = 0; s2 < 2; s2++) {
            int idx = tid + s2 * 256;
            int b = idx >> 3, j = idx & 7;
            float zi  = zf[b * 32 + j];
            float zff = zf[b * 32 + 8 + j];
            float zg  = zf[b * 32 + 16 + j];
            float zo  = zf[b * 32 + 24 + j];
            float ig = 1.f / (1.f + expf(-zi));
            float fg = 1.f / (1.f + expf(-zff));
            float gg = tanhf(zg);
            float og = 1.f / (1.f + expf(-zo));
            float cn = fg * cs[idx] + ig * gg;
            cs[idx] = cn;
            h_out[b * H_ + u0 + j] = og * tanhf(cn);
        }

        // ---- grid-wide barrier (release arrival, acquire spin) ----
        __threadfence();
        __syncthreads();
        if (tid == 0) {
            asm volatile("red.release.gpu.global.add.u32 [%0], 1;"
                         :: "l"(&g_bar[s]) : "memory");
            unsigned v;
            do {
                asm volatile("ld.acquire.gpu.global.u32 %0, [%1];"
                             : "=r"(v) : "l"(&g_bar[s]) : "memory");
            } while (v < NBLK_);
        }
        __syncthreads();
    }

    // ---- persist c state ----
    #pragma unroll
    for (int i = 0; i < 2; i++) {
        int idx = tid + i * 256;
        g_cst[(idx >> 3) * H_ + u0 + (idx & 7)] = cs[idx];
    }
}

// ------------------------------- output -------------------------------------
// After t=511, h lives in g_hbuf[(511+1)&1] == g_hbuf[0]. Output = [h_T ; c_T].
__global__ void write_out(float* __restrict__ out) {
    int i = blockIdx.x * blockDim.x + threadIdx.x;
    if (i < B_ * H_) {
        out[i] = g_hbuf[0][i];
        out[B_ * H_ + i] = g_cst[i];
    }
}

extern "C" void kernel_launch(void* const* d_in, const int* in_sizes, int n_in,
                              void* d_out, int out_size) {
    (void)in_sizes; (void)n_in; (void)out_size;
    const int*   src  = (const int*)d_in[0];
    const float* emb  = (const float*)d_in[1];
    const float* Wih  = (const float*)d_in[2];
    const float* Whh  = (const float*)d_in[3];
    const float* bias = (const float*)d_in[4];
    float* out = (float*)d_out;

    cudaFuncSetAttribute(lstm_chunk, cudaFuncAttributeMaxDynamicSharedMemorySize,
                         SMEM_BYTES_);

    init_state<<<(B_ * H_ + 255) / 256, 256>>>();
    for (int t0 = 0; t0 < T_; t0 += TCH_) {
        xproj_gemm<<<dim3(G4_ / 64, (TCH_ * B_) / 128), 256>>>(src, emb, Wih,
                                                               bias, t0);
        lstm_chunk<<<NBLK_, 256, SMEM_BYTES_>>>(Whh, t0);
    }
    write_out<<<(B_ * H_ + 255) / 256, 256>>>(out);
}